// round 2
// baseline (speedup 1.0000x reference)
#include <cuda_runtime.h>
#include <cstdint>

// Problem shape (fixed by the dataset)
#define B  8
#define T  4096
#define D  1024
#define TT 16                       // rows per tile
#define V4 (D / 4)                  // 256 float4 columns
#define THREADS V4                  // one float4 column per thread
#define TILES_PER_B (T / TT)        // 256
#define NTILES (B * TILES_PER_B)    // 2048
#define SMEM_BYTES (TT * V4 * 16)   // 65536

// Scratch (no allocations allowed — static __device__ globals)
__device__ float4 g_agg [NTILES * V4];
__device__ float4 g_incl[NTILES * V4];
__device__ int    g_flags[NTILES];
__device__ unsigned int g_ticket;

__device__ __forceinline__ void st_release(int* p, int v) {
    asm volatile("st.global.release.gpu.s32 [%0], %1;" :: "l"(p), "r"(v) : "memory");
}
__device__ __forceinline__ int ld_acquire(const int* p) {
    int v;
    asm volatile("ld.global.acquire.gpu.s32 %0, [%1];" : "=r"(v) : "l"(p) : "memory");
    return v;
}

__device__ __forceinline__ float gelu_exact(float x) {
    // jax.nn.gelu(approximate=False) == x * Phi(x)
    return x * normcdff(x);
}

// lengths dtype sniffing: reference asks for int64 but JAX default config
// (x64 disabled) emits int32. Reading the first 8 int32 words is safe under
// BOTH layouts (>= 32 bytes present). If the buffer is genuine int64, every
// odd 32-bit word is the zero high-half (lengths < 4096 << 2^31). If it is
// int32, odd words are random lengths in [0, 4096). Deterministic for the
// fixed bench input.
__device__ __forceinline__ long long load_length(const void* lp, int b) {
    const int* p32 = (const int*)lp;
    bool is64 = (p32[1] == 0) & (p32[3] == 0) & (p32[5] == 0) & (p32[7] == 0);
    if (is64) return ((const long long*)lp)[b];
    return (long long)p32[b];
}

__global__ void init_kernel() {
    int i = blockIdx.x * blockDim.x + threadIdx.x;
    if (i < NTILES) g_flags[i] = 0;
    if (i == 0) g_ticket = 0u;
}

__global__ void __launch_bounds__(THREADS)
scan_kernel(const float* __restrict__ x,
            const void* __restrict__ lengths,
            float* __restrict__ out) {
    extern __shared__ float4 c_smem[];           // [TT][V4]
    __shared__ unsigned sh_v;
    __shared__ int sh_flag;

    const int tid = threadIdx.x;

    // Ticket: guarantees tiles are acquired in increasing order => lookback
    // predecessors are always resident or finished (no deadlock).
    if (tid == 0) sh_v = atomicAdd(&g_ticket, 1u);
    __syncthreads();
    const unsigned v = sh_v;
    const int b  = v / TILES_PER_B;
    const int p  = v % TILES_PER_B;
    const int t0 = p * TT;
    const long long len = load_length(lengths, b);

    const float4* x4 = reinterpret_cast<const float4*>(x)
                       + ((size_t)b * T + t0) * V4 + tid;

    // ---- Loop 1: load x once, gelu once, local prefix, stash c in smem ----
    float4 sum = make_float4(0.f, 0.f, 0.f, 0.f);
    #pragma unroll
    for (int t = 0; t < TT; t++) {
        float4 xv = x4[t * V4];
        float4 c;
        if ((long long)(t0 + t) < len) {          // block-uniform branch
            sum.x += gelu_exact(xv.x);
            sum.y += gelu_exact(xv.y);
            sum.z += gelu_exact(xv.z);
            sum.w += gelu_exact(xv.w);
            c.x = xv.x + sum.x;
            c.y = xv.y + sum.y;
            c.z = xv.z + sum.z;
            c.w = xv.w + sum.w;
        } else {
            c = xv;                                // masked row: out = x
        }
        c_smem[t * V4 + tid] = c;
    }

    // ---- Publish aggregate / inclusive, decoupled lookback ----
    const size_t base = (size_t)v * V4 + tid;
    float4 excl = make_float4(0.f, 0.f, 0.f, 0.f);

    if (p == 0) {
        g_incl[base] = sum;
        __syncthreads();
        if (tid == 0) { __threadfence(); st_release(&g_flags[v], 2); }
    } else {
        g_agg[base] = sum;
        __syncthreads();
        if (tid == 0) { __threadfence(); st_release(&g_flags[v], 1); }

        int vj = (int)v - 1;
        while (true) {
            if (tid == 0) {
                int f = ld_acquire(&g_flags[vj]);
                while (f == 0) { __nanosleep(40); f = ld_acquire(&g_flags[vj]); }
                sh_flag = f;
            }
            __syncthreads();
            const int f = sh_flag;
            __syncthreads();   // allow sh_flag reuse next iteration
            const float4* src = (f == 2 ? g_incl : g_agg) + (size_t)vj * V4 + tid;
            float4 a = *src;
            excl.x += a.x; excl.y += a.y; excl.z += a.z; excl.w += a.w;
            if (f == 2) break;
            vj--;
        }

        float4 inc;
        inc.x = excl.x + sum.x; inc.y = excl.y + sum.y;
        inc.z = excl.z + sum.z; inc.w = excl.w + sum.w;
        g_incl[base] = inc;
        __syncthreads();
        if (tid == 0) { __threadfence(); st_release(&g_flags[v], 2); }
    }

    // ---- Loop 2: out = c + valid * excl ----
    float4* o4 = reinterpret_cast<float4*>(out) + ((size_t)b * T + t0) * V4 + tid;
    #pragma unroll
    for (int t = 0; t < TT; t++) {
        float4 c = c_smem[t * V4 + tid];
        float4 o;
        if ((long long)(t0 + t) < len) {          // block-uniform
            o.x = c.x + excl.x; o.y = c.y + excl.y;
            o.z = c.z + excl.z; o.w = c.w + excl.w;
        } else {
            o = c;
        }
        o4[t * V4] = o;
    }
}

extern "C" void kernel_launch(void* const* d_in, const int* in_sizes, int n_in,
                              void* d_out, int out_size) {
    const float* x   = (const float*)d_in[0];
    const void*  len = (const void*)d_in[1];
    float*       out = (float*)d_out;

    cudaFuncSetAttribute(scan_kernel,
                         cudaFuncAttributeMaxDynamicSharedMemorySize, SMEM_BYTES);

    init_kernel<<<(NTILES + 255) / 256, 256>>>();
    scan_kernel<<<NTILES, THREADS, SMEM_BYTES>>>(x, len, out);
}

// round 3
// speedup vs baseline: 1.2113x; 1.2113x over previous
#include <cuda_runtime.h>
#include <cstdint>

// Problem shape (fixed by the dataset)
#define B  8
#define T  4096
#define D  1024
#define V4D (D / 4)                 // 256 float4 per full row

// Tiling: each CTA owns (batch, 128-float D-slice, 128 rows)
#define SLICES     8                // D / 128
#define SLICE_V4   32               // 128 floats = 32 float4
#define TILE_ROWS  128
#define GROUPS     8                // row groups per CTA
#define RPG        16               // rows per group
#define THREADS    256              // 8 groups x 32 columns
#define TILES      (T / TILE_ROWS)  // 32 tiles per chain
#define NCHAINS    (B * SLICES)     // 64 independent chains
#define NTILES     (NCHAINS * TILES)// 2048 CTAs

// dynamic smem layout (float4 units)
#define SM_C       0                                  // [TILE_ROWS][SLICE_V4]
#define SM_PART    (TILE_ROWS * SLICE_V4)             // [GROUPS][SLICE_V4]
#define SM_AGG     (SM_PART + GROUPS * SLICE_V4)      // [SLICE_V4]
#define SM_EXCL    (SM_AGG + SLICE_V4)                // [SLICE_V4]
#define SMEM_F4    (SM_EXCL + SLICE_V4)
#define SMEM_BYTES (SMEM_F4 * 16)                     // 70656 B

// Scratch (no allocations allowed — static __device__ globals)
__device__ float4 g_agg [NTILES * SLICE_V4];
__device__ float4 g_incl[NTILES * SLICE_V4];
__device__ int    g_flags[NTILES];
__device__ unsigned int g_ticket;

__device__ __forceinline__ void st_release(int* p, int v) {
    asm volatile("st.global.release.gpu.s32 [%0], %1;" :: "l"(p), "r"(v) : "memory");
}
__device__ __forceinline__ int ld_acquire(const int* p) {
    int v;
    asm volatile("ld.global.acquire.gpu.s32 %0, [%1];" : "=r"(v) : "l"(p) : "memory");
    return v;
}

__device__ __forceinline__ float gelu_exact(float x) {
    // jax.nn.gelu(approximate=False) == x * Phi(x)
    return x * normcdff(x);
}

// lengths dtype sniffing: reference asks for int64 but JAX default config
// (x64 disabled) emits int32. Reading the first 8 int32 words is safe under
// BOTH layouts. If genuine int64, every odd 32-bit word is the zero
// high-half (lengths < 4096). If int32, odd words are random lengths.
__device__ __forceinline__ long long load_length(const void* lp, int b) {
    const int* p32 = (const int*)lp;
    bool is64 = (p32[1] == 0) & (p32[3] == 0) & (p32[5] == 0) & (p32[7] == 0);
    if (is64) return ((const long long*)lp)[b];
    return (long long)p32[b];
}

__global__ void init_kernel() {
    int i = blockIdx.x * blockDim.x + threadIdx.x;
    if (i < NTILES) g_flags[i] = 0;
    if (i == 0) g_ticket = 0u;
}

__global__ void __launch_bounds__(THREADS)
scan_kernel(const float* __restrict__ x,
            const void* __restrict__ lengths,
            float* __restrict__ out) {
    extern __shared__ float4 smem[];
    __shared__ unsigned sh_v;

    const int tid = threadIdx.x;
    const int col = tid & 31;       // float4 column within slice
    const int grp = tid >> 5;       // row group (== warp id)

    // Ticket: tiles acquired in increasing order => lookback predecessors are
    // already running or finished (no deadlock under graph replay).
    if (tid == 0) sh_v = atomicAdd(&g_ticket, 1u);
    __syncthreads();
    const unsigned v = sh_v;
    const int chain = v / TILES;    // (b, slice)
    const int p     = v % TILES;
    const int b     = chain / SLICES;
    const int s     = chain % SLICES;
    const int t0    = p * TILE_ROWS;
    const long long len = load_length(lengths, b);

    // gmem base for this thread: row (t0 + grp*RPG), slice s, column col
    const size_t row0 = (size_t)b * T + t0 + grp * RPG;
    const float4* x4 = reinterpret_cast<const float4*>(x)
                       + row0 * V4D + s * SLICE_V4 + col;

    // ---- Pass 1: load x once, gelu once, register-serial group prefix ----
    float4 run = make_float4(0.f, 0.f, 0.f, 0.f);
    #pragma unroll
    for (int i = 0; i < RPG; i++) {
        const int row = t0 + grp * RPG + i;
        float4 xv = x4[(size_t)i * V4D];
        float4 c;
        if ((long long)row < len) {           // warp-uniform branch
            run.x += gelu_exact(xv.x);
            run.y += gelu_exact(xv.y);
            run.z += gelu_exact(xv.z);
            run.w += gelu_exact(xv.w);
            c.x = xv.x + run.x; c.y = xv.y + run.y;
            c.z = xv.z + run.z; c.w = xv.w + run.w;
        } else {
            c = xv;                            // masked row: out = x
        }
        smem[SM_C + (grp * RPG + i) * SLICE_V4 + col] = c;
    }
    smem[SM_PART + grp * SLICE_V4 + col] = run;
    __syncthreads();

    // ---- group-exclusive offsets (<=7 smem reads per thread) ----
    float4 gex = make_float4(0.f, 0.f, 0.f, 0.f);
    for (int g = 0; g < grp; g++) {
        float4 a = smem[SM_PART + g * SLICE_V4 + col];
        gex.x += a.x; gex.y += a.y; gex.z += a.z; gex.w += a.w;
    }

    // ---- warp 7 publishes tile aggregate ----
    const size_t abase = (size_t)v * SLICE_V4 + col;
    if (grp == GROUPS - 1) {
        float4 agg;
        agg.x = gex.x + run.x; agg.y = gex.y + run.y;
        agg.z = gex.z + run.z; agg.w = gex.w + run.w;
        smem[SM_AGG + col] = agg;
        if (p == 0) {
            g_incl[abase] = agg;
            __syncwarp();
            if (col == 0) { __threadfence(); st_release(&g_flags[v], 2); }
        } else {
            g_agg[abase] = agg;
            __syncwarp();
            if (col == 0) { __threadfence(); st_release(&g_flags[v], 1); }
        }
    }
    __syncthreads();   // SM_AGG visible to warp 0

    // ---- warp 0: decoupled lookback (warp-only, no block syncs) ----
    if (grp == 0) {
        float4 excl = make_float4(0.f, 0.f, 0.f, 0.f);
        if (p > 0) {
            int vj = (int)v - 1;
            while (true) {
                int f;
                if (col == 0) {
                    f = ld_acquire(&g_flags[vj]);
                    while (f == 0) { __nanosleep(20); f = ld_acquire(&g_flags[vj]); }
                }
                f = __shfl_sync(0xffffffffu, f, 0);
                const float4* src = (f == 2 ? g_incl : g_agg)
                                    + (size_t)vj * SLICE_V4 + col;
                float4 a = *src;
                excl.x += a.x; excl.y += a.y; excl.z += a.z; excl.w += a.w;
                if (f == 2) break;
                vj--;
            }
            // publish inclusive ASAP (critical path of the chain)
            float4 agg = smem[SM_AGG + col];
            float4 inc;
            inc.x = excl.x + agg.x; inc.y = excl.y + agg.y;
            inc.z = excl.z + agg.z; inc.w = excl.w + agg.w;
            g_incl[abase] = inc;
            __syncwarp();
            if (col == 0) { __threadfence(); st_release(&g_flags[v], 2); }
        }
        smem[SM_EXCL + col] = excl;
    }
    __syncthreads();

    // ---- Pass 2: out = c + valid * (chain_excl + group_excl) ----
    float4 off = smem[SM_EXCL + col];
    off.x += gex.x; off.y += gex.y; off.z += gex.z; off.w += gex.w;

    float4* o4 = reinterpret_cast<float4*>(out)
                 + row0 * V4D + s * SLICE_V4 + col;
    #pragma unroll
    for (int i = 0; i < RPG; i++) {
        const int row = t0 + grp * RPG + i;
        float4 c = smem[SM_C + (grp * RPG + i) * SLICE_V4 + col];
        float4 o;
        if ((long long)row < len) {           // warp-uniform
            o.x = c.x + off.x; o.y = c.y + off.y;
            o.z = c.z + off.z; o.w = c.w + off.w;
        } else {
            o = c;
        }
        o4[(size_t)i * V4D] = o;
    }
}

extern "C" void kernel_launch(void* const* d_in, const int* in_sizes, int n_in,
                              void* d_out, int out_size) {
    const float* x   = (const float*)d_in[0];
    const void*  len = (const void*)d_in[1];
    float*       out = (float*)d_out;

    cudaFuncSetAttribute(scan_kernel,
                         cudaFuncAttributeMaxDynamicSharedMemorySize, SMEM_BYTES);

    init_kernel<<<(NTILES + 255) / 256, 256>>>();
    scan_kernel<<<NTILES, THREADS, SMEM_BYTES>>>(x, len, out);
}

// round 4
// speedup vs baseline: 1.8578x; 1.5337x over previous
#include <cuda_runtime.h>
#include <cstdint>

// Problem shape (fixed by the dataset)
#define B  8
#define T  4096
#define D  1024
#define V4D (D / 4)                 // 256 float4 per full row

// Tiling: each CTA owns (batch, 128-float D-slice, 128 rows)
#define SLICES     8                // D / 128
#define SLICE_V4   32               // 128 floats = 32 float4
#define TILE_ROWS  128
#define GROUPS     8                // row groups per CTA (== warps)
#define RPG        16               // rows per group
#define CHUNK      4                // load batch (MLP)
#define THREADS    256
#define TILES      (T / TILE_ROWS)  // 32 tiles per chain
#define NCHAINS    (B * SLICES)     // 64 independent chains
#define NTILES     (NCHAINS * TILES)// 2048 CTAs

// dynamic smem layout (float4 units)
#define SM_C       0                                  // [TILE_ROWS][SLICE_V4]
#define SM_PART    (TILE_ROWS * SLICE_V4)             // [GROUPS][SLICE_V4]
#define SMEM_F4    (SM_PART + GROUPS * SLICE_V4)
#define SMEM_BYTES (SMEM_F4 * 16)                     // 69632 B

// Scratch (no allocations allowed — static __device__ globals)
__device__ float4 g_agg [NTILES * SLICE_V4];
__device__ int    g_flags[NTILES];
__device__ unsigned int g_ticket;

__device__ __forceinline__ void st_release(int* p, int v) {
    asm volatile("st.global.release.gpu.s32 [%0], %1;" :: "l"(p), "r"(v) : "memory");
}
__device__ __forceinline__ int ld_acquire(const int* p) {
    int v;
    asm volatile("ld.global.acquire.gpu.s32 %0, [%1];" : "=r"(v) : "l"(p) : "memory");
    return v;
}

// exact gelu via erff (polynomial, no MUFU exp path):
// jax.nn.gelu(approximate=False) = 0.5*x*(1+erf(x/sqrt(2)))
__device__ __forceinline__ float gelu_exact(float x) {
    return 0.5f * x * (1.0f + erff(x * 0.7071067811865475f));
}

// lengths dtype sniffing: reference asks for int64 but JAX default config
// (x64 disabled) emits int32. Reading the first 8 int32 words is safe under
// BOTH layouts. If genuine int64, every odd 32-bit word is the zero
// high-half (lengths < 4096). If int32, odd words are random lengths.
__device__ __forceinline__ int load_length(const void* lp, int b) {
    const int* p32 = (const int*)lp;
    bool is64 = (p32[1] == 0) & (p32[3] == 0) & (p32[5] == 0) & (p32[7] == 0);
    if (is64) return (int)((const long long*)lp)[b];
    return p32[b];
}

__global__ void init_kernel() {
    int i = blockIdx.x * blockDim.x + threadIdx.x;
    if (i < NTILES) g_flags[i] = 0;
    if (i == 0) g_ticket = 0u;
}

__global__ void __launch_bounds__(THREADS)
scan_kernel(const float* __restrict__ x,
            const void* __restrict__ lengths,
            float* __restrict__ out) {
    extern __shared__ float4 smem[];
    __shared__ unsigned sh_v;

    const int tid = threadIdx.x;
    const int col = tid & 31;       // float4 column within slice
    const int grp = tid >> 5;       // row group (== warp id)

    // Ticket: tiles acquired in increasing order => all predecessors of any
    // running tile are resident or finished (no deadlock under graph replay).
    if (tid == 0) sh_v = atomicAdd(&g_ticket, 1u);
    __syncthreads();
    const unsigned v = sh_v;
    const int chain = v / TILES;    // (b, slice)
    const int p     = v % TILES;
    const int chain_base = chain * TILES;
    const int b     = chain / SLICES;
    const int s     = chain % SLICES;
    const int t0    = p * TILE_ROWS;
    const int len   = load_length(lengths, b);

    // gmem base for this thread: row (t0 + grp*RPG), slice s, column col
    const size_t row0 = (size_t)b * T + t0 + grp * RPG;
    const float4* x4 = reinterpret_cast<const float4*>(x)
                       + row0 * V4D + s * SLICE_V4 + col;

    // ---- Pass 1: load x once, gelu once, register-serial group prefix ----
    float4 run = make_float4(0.f, 0.f, 0.f, 0.f);
    #pragma unroll
    for (int i0 = 0; i0 < RPG; i0 += CHUNK) {
        float4 xv[CHUNK];
        #pragma unroll
        for (int k = 0; k < CHUNK; k++)            // batched loads: MLP >= 4
            xv[k] = x4[(size_t)(i0 + k) * V4D];
        #pragma unroll
        for (int k = 0; k < CHUNK; k++) {
            const int row = t0 + grp * RPG + i0 + k;
            float4 c;
            if (row < len) {                        // warp-uniform branch
                run.x += gelu_exact(xv[k].x);
                run.y += gelu_exact(xv[k].y);
                run.z += gelu_exact(xv[k].z);
                run.w += gelu_exact(xv[k].w);
                c.x = xv[k].x + run.x; c.y = xv[k].y + run.y;
                c.z = xv[k].z + run.z; c.w = xv[k].w + run.w;
            } else {
                c = xv[k];                          // masked row: out = x
            }
            smem[SM_C + (grp * RPG + i0 + k) * SLICE_V4 + col] = c;
        }
    }
    smem[SM_PART + grp * SLICE_V4 + col] = run;
    __syncthreads();

    // ---- group-exclusive offsets (<=7 LDS.128 per thread) ----
    float4 gex = make_float4(0.f, 0.f, 0.f, 0.f);
    for (int g = 0; g < grp; g++) {
        float4 a = smem[SM_PART + g * SLICE_V4 + col];
        gex.x += a.x; gex.y += a.y; gex.z += a.z; gex.w += a.w;
    }

    // ---- warp 7 publishes tile aggregate (release) ----
    if (grp == GROUPS - 1) {
        float4 agg;
        agg.x = gex.x + run.x; agg.y = gex.y + run.y;
        agg.z = gex.z + run.z; agg.w = gex.w + run.w;
        g_agg[(size_t)v * SLICE_V4 + col] = agg;
        __syncwarp();
        if (col == 0) { __threadfence(); st_release(&g_flags[v], 1); }
    }

    // ---- parallel gather of ALL predecessor aggregates ----
    float4 excl = make_float4(0.f, 0.f, 0.f, 0.f);
    if (p > 0) {                                    // block-uniform branch
        // warp 0: poll all p predecessor flags concurrently (acquire)
        if (grp == 0 && col < p) {
            const int* fp = &g_flags[chain_base + col];
            int f = ld_acquire(fp);
            while (f == 0) { __nanosleep(20); f = ld_acquire(fp); }
        }
        __syncthreads();   // flags observed; SM_PART (gex) reads complete

        // all 8 warps gather: warp w takes predecessors w, w+8, w+16, w+24
        float4 part = make_float4(0.f, 0.f, 0.f, 0.f);
        for (int j = grp; j < p; j += GROUPS) {
            float4 a = g_agg[(size_t)(chain_base + j) * SLICE_V4 + col];
            part.x += a.x; part.y += a.y; part.z += a.z; part.w += a.w;
        }
        smem[SM_PART + grp * SLICE_V4 + col] = part;   // reuse SM_PART
        __syncthreads();
        #pragma unroll
        for (int w = 0; w < GROUPS; w++) {
            float4 a = smem[SM_PART + w * SLICE_V4 + col];
            excl.x += a.x; excl.y += a.y; excl.z += a.z; excl.w += a.w;
        }
    }

    // ---- Pass 2: out = c + valid * (chain_excl + group_excl) ----
    float4 off;
    off.x = excl.x + gex.x; off.y = excl.y + gex.y;
    off.z = excl.z + gex.z; off.w = excl.w + gex.w;

    float4* o4 = reinterpret_cast<float4*>(out)
                 + row0 * V4D + s * SLICE_V4 + col;
    #pragma unroll
    for (int i = 0; i < RPG; i++) {
        const int row = t0 + grp * RPG + i;
        float4 c = smem[SM_C + (grp * RPG + i) * SLICE_V4 + col];
        float4 o;
        if (row < len) {                            // warp-uniform
            o.x = c.x + off.x; o.y = c.y + off.y;
            o.z = c.z + off.z; o.w = c.w + off.w;
        } else {
            o = c;
        }
        o4[(size_t)i * V4D] = o;
    }
}

extern "C" void kernel_launch(void* const* d_in, const int* in_sizes, int n_in,
                              void* d_out, int out_size) {
    const float* x   = (const float*)d_in[0];
    const void*  len = (const void*)d_in[1];
    float*       out = (float*)d_out;

    cudaFuncSetAttribute(scan_kernel,
                         cudaFuncAttributeMaxDynamicSharedMemorySize, SMEM_BYTES);

    init_kernel<<<(NTILES + 255) / 256, 256>>>();
    scan_kernel<<<NTILES, THREADS, SMEM_BYTES>>>(x, len, out);
}